// round 10
// baseline (speedup 1.0000x reference)
#include <cuda_runtime.h>
#include <cuda_bf16.h>
#include <math.h>
#include <stdint.h>

// Problem constants (fixed by setup_inputs): B=2048, K=128, D=256
#define BB 2048
#define KK 128
#define DD 256

#define BM 32       // b-rows per block (main kernel)
#define BN 32       // k-cols per block
#define PB 264      // smem row pitch in bf16 units (528 B; 16B-aligned, conflict-free ldmatrix)
#define NTHREADS 256

// Global scratch (allocation-free rule: __device__ arrays)
__device__ __nv_bfloat16 g_yhi[BB * DD];
__device__ __nv_bfloat16 g_ylo[BB * DD];
__device__ __nv_bfloat16 g_zhi[KK * DD];
__device__ __nv_bfloat16 g_zlo[KK * DD];
__device__ float g_y2[BB];
__device__ float g_s[KK], g_t[KK], g_x2[KK], g_xa[KK], g_an2[KK];

__device__ __forceinline__ uint32_t cvta_smem(const void* p) {
    return (uint32_t)__cvta_generic_to_shared(p);
}
__device__ __forceinline__ void ldmat_x4(uint32_t* r, uint32_t addr) {
    asm volatile("ldmatrix.sync.aligned.m8n8.x4.shared.b16 {%0,%1,%2,%3}, [%4];"
                 : "=r"(r[0]), "=r"(r[1]), "=r"(r[2]), "=r"(r[3]) : "r"(addr));
}
__device__ __forceinline__ void mma_bf16(float* d, const uint32_t* a, uint32_t b0, uint32_t b1) {
    asm volatile("mma.sync.aligned.m16n8k16.row.col.f32.bf16.bf16.f32 "
                 "{%0,%1,%2,%3}, {%4,%5,%6,%7}, {%8,%9}, {%0,%1,%2,%3};"
                 : "+f"(d[0]), "+f"(d[1]), "+f"(d[2]), "+f"(d[3])
                 : "r"(a[0]), "r"(a[1]), "r"(a[2]), "r"(a[3]), "r"(b0), "r"(b1));
}
__device__ __forceinline__ uint32_t bits2(__nv_bfloat162 v) {
    return *reinterpret_cast<uint32_t*>(&v);
}

// ============ Kernel 1: split + per-row scalars (one warp per row) ============
__global__ void __launch_bounds__(256, 4)
prep_kernel(const float* __restrict__ Y, const float* __restrict__ Z,
            const float* __restrict__ R)
{
    const int warp = threadIdx.x >> 5;
    const int lane = threadIdx.x & 31;
    const bool isZ = blockIdx.x >= (BB / 8);
    const int row  = isZ ? (blockIdx.x - BB / 8) * 8 + warp : blockIdx.x * 8 + warp;
    if (isZ && row >= KK) return;

    const float* src = (isZ ? Z : Y) + (size_t)row * DD;
    __nv_bfloat16* hiDst = (isZ ? g_zhi : g_yhi) + (size_t)row * DD;
    __nv_bfloat16* loDst = (isZ ? g_zlo : g_ylo) + (size_t)row * DD;

    float acc = 0.f;
    #pragma unroll
    for (int j = 0; j < 2; j++) {
        int c4 = lane + 32 * j;
        float4 v = reinterpret_cast<const float4*>(src)[c4];
        __nv_bfloat162 h01 = __float22bfloat162_rn(make_float2(v.x, v.y));
        __nv_bfloat162 h23 = __float22bfloat162_rn(make_float2(v.z, v.w));
        float2 hf01 = __bfloat1622float2(h01);
        float2 hf23 = __bfloat1622float2(h23);
        __nv_bfloat162 l01 = __float22bfloat162_rn(make_float2(v.x - hf01.x, v.y - hf01.y));
        __nv_bfloat162 l23 = __float22bfloat162_rn(make_float2(v.z - hf23.x, v.w - hf23.y));
        reinterpret_cast<uint2*>(hiDst)[c4] = make_uint2(bits2(h01), bits2(h23));
        reinterpret_cast<uint2*>(loDst)[c4] = make_uint2(bits2(l01), bits2(l23));
        // norm from representable value hi+lo
        float2 lf01 = __bfloat1622float2(l01);
        float2 lf23 = __bfloat1622float2(l23);
        float v0 = hf01.x + lf01.x, v1 = hf01.y + lf01.y;
        float v2 = hf23.x + lf23.x, v3 = hf23.y + lf23.y;
        acc = fmaf(v0, v0, acc); acc = fmaf(v1, v1, acc);
        acc = fmaf(v2, v2, acc); acc = fmaf(v3, v3, acc);
    }
    #pragma unroll
    for (int off = 16; off > 0; off >>= 1)
        acc += __shfl_xor_sync(0xffffffffu, acc, off);

    if (lane == 0) {
        if (!isZ) {
            g_y2[row] = acc;
        } else {
            float zn2 = acc;
            float zn  = sqrtf(zn2);
            float r   = R[row];
            float un  = fmaxf(fabsf(r) * zn, 1e-15f);
            float s   = -tanhf(un) * r / un;
            float th  = tanhf(r);
            float ic2 = 1.0f - th * th;      // 1/cosh(r)^2
            float an  = zn * ic2;
            float t   = ic2 / fmaxf(an, 1e-12f);
            g_s[row]   = s;
            g_t[row]   = t;
            g_x2[row]  = s * s * zn2;
            g_xa[row]  = s * zn2 * t;
            g_an2[row] = 2.0f * an;
        }
    }
}

// ============ Kernel 2: bf16 3-term MMA GEMM + hyperbolic epilogue ============
// logits[b][k] = 2*an_k * asinh( 2*(S*xa + T*ya)*den / (den^2 - (S^2*x2 + 2*S*T*xy + T^2*y2)) )
// g = z_k . y_b, xy = s_k*g, ya = t_k*g, S = 1+2xy+y2, den = 1+2xy+x2*y2, T = 1-x2

__global__ void __launch_bounds__(NTHREADS, 2)
mlr_logits_kernel(float* __restrict__ Out)       // (B, K)
{
    extern __shared__ char smem[];
    __nv_bfloat16* AHI = reinterpret_cast<__nv_bfloat16*>(smem);           // BM*PB
    __nv_bfloat16* ALO = AHI + BM * PB;                                     // BM*PB
    __nv_bfloat16* ZHI = ALO + BM * PB;                                     // BN*PB
    __nv_bfloat16* ZLO = ZHI + BN * PB;                                     // BN*PB
    float* s_s   = reinterpret_cast<float*>(ZLO + BN * PB);                 // BN
    float* s_t   = s_s + BN;
    float* s_x2  = s_t + BN;
    float* s_xa  = s_x2 + BN;
    float* s_an2 = s_xa + BN;
    float* s_y2  = s_an2 + BN;                                              // BM

    const int tid  = threadIdx.x;
    const int b0   = blockIdx.x * BM;
    const int k0   = blockIdx.y * BN;
    const int warp = tid >> 5;
    const int lane = tid & 31;

    // ---- copy pre-split tiles gmem -> smem (uint4 = 8 bf16) ----
    // Y tiles: BM rows x 32 uint4/row = 1024 uint4 each
    #pragma unroll
    for (int idx = tid; idx < BM * 32; idx += NTHREADS) {
        int row = idx >> 5;
        int c8  = idx & 31;
        size_t goff = (size_t)(b0 + row) * DD + c8 * 8;
        *reinterpret_cast<uint4*>(&AHI[row * PB + c8 * 8]) =
            *reinterpret_cast<const uint4*>(&g_yhi[goff]);
        *reinterpret_cast<uint4*>(&ALO[row * PB + c8 * 8]) =
            *reinterpret_cast<const uint4*>(&g_ylo[goff]);
    }
    #pragma unroll
    for (int idx = tid; idx < BN * 32; idx += NTHREADS) {
        int row = idx >> 5;
        int c8  = idx & 31;
        size_t goff = (size_t)(k0 + row) * DD + c8 * 8;
        *reinterpret_cast<uint4*>(&ZHI[row * PB + c8 * 8]) =
            *reinterpret_cast<const uint4*>(&g_zhi[goff]);
        *reinterpret_cast<uint4*>(&ZLO[row * PB + c8 * 8]) =
            *reinterpret_cast<const uint4*>(&g_zlo[goff]);
    }
    // ---- stage scalars ----
    if (tid < BM) {
        s_y2[tid] = g_y2[b0 + tid];
    } else if (tid < BM + BN) {
        int row = tid - BM;
        s_s[row]   = g_s[k0 + row];
        s_t[row]   = g_t[k0 + row];
        s_x2[row]  = g_x2[k0 + row];
        s_xa[row]  = g_xa[k0 + row];
        s_an2[row] = g_an2[k0 + row];
    }
    __syncthreads();

    // ---- tensor GEMM: 8 warps (2m x 4n), warp tile 16m x 8n, m16n8k16 bf16 ----
    const int mw = (warp >> 2) * 16;      // 0,16
    const int nw = (warp & 3) * 8;        // 0,8,16,24
    const int g  = lane >> 2;
    const int c  = lane & 3;

    const int rowA = mw + (lane & 15);
    const int offA = (lane >> 4) * 16;             // bytes
    const int rowB = nw + (lane & 7);
    const int offB = (lane >> 3) * 16;             // bytes: 0,16,32,48

    uint32_t aAH = cvta_smem(AHI) + rowA * (PB * 2) + offA;
    uint32_t aAL = cvta_smem(ALO) + rowA * (PB * 2) + offA;
    uint32_t aBH = cvta_smem(ZHI) + rowB * (PB * 2) + offB;
    uint32_t aBL = cvta_smem(ZLO) + rowB * (PB * 2) + offB;

    float accP[4] = {0,0,0,0};   // hi*hi
    float accQ[4] = {0,0,0,0};   // hi*lo
    float accS[4] = {0,0,0,0};   // lo*hi

    #pragma unroll
    for (int t = 0; t < DD / 32; t++) {          // 8 iterations of k32
        const uint32_t oA = t * 64;              // 32 bf16 = 64 bytes
        uint32_t aH0[4], aH1[4], aL0[4], aL1[4], bH[4], bL[4];
        ldmat_x4(aH0, aAH + oA);
        ldmat_x4(aH1, aAH + oA + 32);
        ldmat_x4(aL0, aAL + oA);
        ldmat_x4(aL1, aAL + oA + 32);
        ldmat_x4(bH,  aBH + oA);
        ldmat_x4(bL,  aBL + oA);

        mma_bf16(accP, aH0, bH[0], bH[1]);
        mma_bf16(accQ, aH0, bL[0], bL[1]);
        mma_bf16(accS, aL0, bH[0], bH[1]);
        mma_bf16(accP, aH1, bH[2], bH[3]);
        mma_bf16(accQ, aH1, bL[2], bL[3]);
        mma_bf16(accS, aL1, bH[2], bH[3]);
    }

    // ---- epilogue: 4 outputs per thread, float2 stores ----
    const int brow[2] = { mw + g, mw + g + 8 };
    const int kl = nw + 2 * c;
    const float s0  = s_s[kl],   s1  = s_s[kl + 1];
    const float t0  = s_t[kl],   t1  = s_t[kl + 1];
    const float x20 = s_x2[kl],  x21 = s_x2[kl + 1];
    const float xa0 = s_xa[kl],  xa1 = s_xa[kl + 1];
    const float a20 = s_an2[kl], a21 = s_an2[kl + 1];
    const float T0 = 1.0f - x20, T1 = 1.0f - x21;

    #pragma unroll
    for (int i = 0; i < 2; i++) {
        const float y2 = s_y2[brow[i]];
        const float g0 = accP[i * 2 + 0] + accQ[i * 2 + 0] + accS[i * 2 + 0];
        const float g1 = accP[i * 2 + 1] + accQ[i * 2 + 1] + accS[i * 2 + 1];

        float xy = s0 * g0;
        float ya = t0 * g0;
        float Sv  = fmaf(2.0f, xy, 1.0f) + y2;
        float den = fmaf(2.0f, xy, 1.0f) + x20 * y2;
        float Pv  = Sv * Sv * x20 + 2.0f * Sv * T0 * xy + T0 * T0 * y2;
        float v0  = 2.0f * (Sv * xa0 + T0 * ya) * den / (den * den - Pv);
        float o0  = a20 * asinhf(v0);

        xy  = s1 * g1;
        ya  = t1 * g1;
        Sv  = fmaf(2.0f, xy, 1.0f) + y2;
        den = fmaf(2.0f, xy, 1.0f) + x21 * y2;
        Pv  = Sv * Sv * x21 + 2.0f * Sv * T1 * xy + T1 * T1 * y2;
        float v1 = 2.0f * (Sv * xa1 + T1 * ya) * den / (den * den - Pv);
        float o1 = a21 * asinhf(v1);

        *reinterpret_cast<float2*>(&Out[(size_t)(b0 + brow[i]) * KK + (k0 + kl)]) =
            make_float2(o0, o1);
    }
}

extern "C" void kernel_launch(void* const* d_in, const int* in_sizes, int n_in,
                              void* d_out, int out_size)
{
    const float* Y = (const float*)d_in[0];   // output_before (2048, 256)
    const float* Z = (const float*)d_in[1];   // z_mlr (128, 256)
    const float* R = (const float*)d_in[2];   // mlr_r (128, 1)
    float* Out = (float*)d_out;               // (2048, 128)

    // Kernel 1: split + scalars.  256 Y-blocks + 16 Z-blocks.
    prep_kernel<<<BB / 8 + KK / 8, 256>>>(Y, Z, R);

    // Kernel 2: GEMM + epilogue.
    size_t shmem = (size_t)(2 * BM * PB + 2 * BN * PB) * sizeof(__nv_bfloat16)
                 + (size_t)(5 * BN + BM) * sizeof(float);
    cudaFuncSetAttribute(mlr_logits_kernel,
                         cudaFuncAttributeMaxDynamicSharedMemorySize, (int)shmem);
    dim3 grid(BB / BM, KK / BN);   // 64 x 4 = 256 blocks
    mlr_logits_kernel<<<grid, NTHREADS, shmem>>>(Out);
}